// round 17
// baseline (speedup 1.0000x reference)
#include <cuda_runtime.h>
#include <math.h>
#include <stdint.h>

// ---------------------------------------------------------------------------
// Problem constants
// ---------------------------------------------------------------------------
constexpr int Bb   = 8;
constexpr int Tt   = 1024;
constexpr int Cc   = 768;
constexpr int NHh  = 12;
constexpr int HSz  = 64;
constexpr int MR   = Bb * Tt;      // 8192 rows
constexpr int FFd  = 4 * Cc;       // 3072
constexpr int QKVN = 3 * Cc;       // 2304

// u32 (half2) row strides
constexpr int CU   = Cc / 2;       // 384
constexpr int QKVU = QKVN / 2;     // 1152
constexpr int FFU  = FFd / 2;      // 1536

// ---------------------------------------------------------------------------
// Scratch (device globals). fp16 data stored as uint32_t = half2 (k-pairs).
// ---------------------------------------------------------------------------
__device__ uint32_t g_h   [(size_t)MR * CU];      // LN1 out
__device__ uint32_t g_qkv [(size_t)MR * QKVU];    // fused qkv out
__device__ uint32_t g_o   [(size_t)MR * CU];      // attn out
__device__ float    g_x2  [(size_t)MR * Cc];      // residual stream (fp32)
__device__ uint32_t g_h2  [(size_t)MR * CU];      // LN2 out
__device__ uint32_t g_ff  [(size_t)MR * FFU];     // gelu out
__device__ uint32_t g_wqkv[(size_t)CU * QKVN];    // packed Wq|Wk|Wv, k-pairs
__device__ uint32_t g_wo  [(size_t)CU * Cc];
__device__ uint32_t g_w1  [(size_t)CU * FFd];
__device__ uint32_t g_w2  [(size_t)FFU * Cc];

// pack two fp32 -> half2 u32 {lo, hi}
__device__ __forceinline__ uint32_t f2h2(float lo, float hi) {
    uint32_t d;
    asm("cvt.rn.f16x2.f32 %0, %1, %2;" : "=r"(d) : "f"(hi), "f"(lo));
    return d;
}

// ---------------------------------------------------------------------------
// Weight convert: fp32 [K][Nin] -> k-pair-packed half2 u32 [K/2][ldout] at off
// ---------------------------------------------------------------------------
__global__ __launch_bounds__(256) void cvt_pack_kernel(
    const float* __restrict__ in, uint32_t* __restrict__ out,
    int Nin, int ldout, int off, int total)
{
    int i = blockIdx.x * 256 + threadIdx.x;
    if (i >= total) return;
    int kk = i / Nin;
    int n  = i - kk * Nin;
    float a = in[(size_t)(2 * kk)     * Nin + n];
    float b = in[(size_t)(2 * kk + 1) * Nin + n];
    out[(size_t)kk * ldout + off + n] = f2h2(a, b);
}

// ---------------------------------------------------------------------------
// LayerNorm: warp-per-row (8 rows per 256-thread CTA, no block syncs).
// Each lane owns 6 float4 chunks at stride-32 (coalesced). Writes half2.
// ---------------------------------------------------------------------------
__global__ __launch_bounds__(256) void ln_kernel(
    const float* __restrict__ X, const float* __restrict__ g,
    const float* __restrict__ be, uint32_t* __restrict__ Y)
{
    int warp = threadIdx.x >> 5;
    int lane = threadIdx.x & 31;
    int row  = blockIdx.x * 8 + warp;

    const float4* xr = (const float4*)(X + (size_t)row * Cc);
    float4 v[6];
    float s = 0.f;
    #pragma unroll
    for (int i = 0; i < 6; i++) {
        v[i] = xr[i * 32 + lane];
        s += v[i].x + v[i].y + v[i].z + v[i].w;
    }
    #pragma unroll
    for (int off = 16; off > 0; off >>= 1)
        s += __shfl_xor_sync(0xffffffffu, s, off);
    float mu = s * (1.0f / Cc);

    float sq = 0.f;
    #pragma unroll
    for (int i = 0; i < 6; i++) {
        float d0 = v[i].x - mu, d1 = v[i].y - mu;
        float d2 = v[i].z - mu, d3 = v[i].w - mu;
        sq += d0 * d0 + d1 * d1 + d2 * d2 + d3 * d3;
    }
    #pragma unroll
    for (int off = 16; off > 0; off >>= 1)
        sq += __shfl_xor_sync(0xffffffffu, sq, off);
    float inv = rsqrtf(sq * (1.0f / Cc) + 1e-5f);

    uint32_t* yr = Y + (size_t)row * CU;
    #pragma unroll
    for (int i = 0; i < 6; i++) {
        int c4 = i * 32 + lane;
        float4 gg = ((const float4*)g)[c4];
        float4 bb = ((const float4*)be)[c4];
        float y0 = (v[i].x - mu) * inv * gg.x + bb.x;
        float y1 = (v[i].y - mu) * inv * gg.y + bb.y;
        float y2 = (v[i].z - mu) * inv * gg.z + bb.z;
        float y3 = (v[i].w - mu) * inv * gg.w + bb.w;
        uint2 o;
        o.x = f2h2(y0, y1); o.y = f2h2(y2, y3);
        *(uint2*)(yr + c4 * 2) = o;
    }
}

// ---------------------------------------------------------------------------
// FP16 tensor-core GEMM: C[M,N] = A[M,K] @ B[K,N]; A/B half2-packed u32.
// KU = K/2 (u32 units). 128x128 CTA tile, k-tile = 32 u32 = 64 halves.
// 8 warps (2x4), warp tile 64x32 via m16n8k16. 3-stage cp.async,
// single __syncthreads per k-tile (prefetch issued post-sync).
// EP: 0 = plain, 1 = resid+bias (fp32 out), 2 = gelu(acc+bias)
// OH: 0 = fp32 out, 1 = half2 out
// ---------------------------------------------------------------------------
constexpr int GBK      = 32;     // u32 per k-tile (= 64 halves)
constexpr int GSTAGES  = 3;
constexpr int A_STRIDE = 36;     // 32 data + 4 pad (144 B, 16B-mult)
constexpr int B_STRIDE = 132;    // 128 data + 4 pad
constexpr int A_STAGE  = 128 * A_STRIDE;          // 4608 u32
constexpr int B_STAGE  = GBK * B_STRIDE;          // 4224 u32
constexpr int STAGE_U32 = A_STAGE + B_STAGE;      // 8832 u32
constexpr int GEMM_SMEM = GSTAGES * STAGE_U32 * 4; // 105984 B

__device__ __forceinline__ void cpa16(uint32_t* s, const uint32_t* g) {
    uint32_t sa = (uint32_t)__cvta_generic_to_shared(s);
    asm volatile("cp.async.cg.shared.global [%0], [%1], 16;\n"
                 :: "r"(sa), "l"(g));
}

__device__ __forceinline__ void mma_f16(
    float c[4], uint32_t a0, uint32_t a1, uint32_t a2, uint32_t a3,
    uint32_t b0, uint32_t b1)
{
    asm volatile(
        "mma.sync.aligned.m16n8k16.row.col.f32.f16.f16.f32 "
        "{%0,%1,%2,%3}, {%4,%5,%6,%7}, {%8,%9}, {%0,%1,%2,%3};"
        : "+f"(c[0]), "+f"(c[1]), "+f"(c[2]), "+f"(c[3])
        : "r"(a0), "r"(a1), "r"(a2), "r"(a3), "r"(b0), "r"(b1));
}

template<int EP, int OH>
__global__ __launch_bounds__(256) void gemm_tc(
    const uint32_t* __restrict__ A, const uint32_t* __restrict__ Bm,
    const float* __restrict__ bias, const float* __restrict__ resid,
    void* __restrict__ Cout, int M, int N, int KU)
{
    extern __shared__ uint32_t sm[];

    int tid  = threadIdx.x;
    int bm   = blockIdx.y * 128;
    int bn   = blockIdx.x * 128;
    int warp = tid >> 5;
    int lane = tid & 31;
    int wm   = warp >> 2;
    int wn   = warp & 3;
    int q    = lane & 3;
    int g    = lane >> 2;

    const uint32_t* Ag = A  + (size_t)bm * KU;
    const uint32_t* Bg = Bm + bn;

    float acc[4][4][4];
    #pragma unroll
    for (int mt = 0; mt < 4; mt++)
        #pragma unroll
        for (int nt = 0; nt < 4; nt++)
            #pragma unroll
            for (int r = 0; r < 4; r++) acc[mt][nt][r] = 0.f;

    const int KT = KU / GBK;

    auto prefetch = [&](int stage, int k0) {
        uint32_t* sA = sm + stage * STAGE_U32;
        uint32_t* sB = sA + A_STAGE;
        #pragma unroll
        for (int i = 0; i < 4; i++) {
            int id = tid + i * 256;          // 0..1023 uint4s (A: 128x32 u32)
            int r  = id >> 3;                // 0..127
            int c  = (id & 7) << 2;          // 0,4,..,28
            cpa16(&sA[r * A_STRIDE + c], Ag + (size_t)r * KU + k0 + c);
        }
        #pragma unroll
        for (int i = 0; i < 4; i++) {
            int id = tid + i * 256;          // 0..1023 uint4s (B: 32x128 u32)
            int r  = id >> 5;                // 0..31
            int c  = (id & 31) << 2;         // 0..124
            cpa16(&sB[r * B_STRIDE + c], Bg + (size_t)(k0 + r) * N + c);
        }
    };

    // prologue: stages 0,1
    prefetch(0, 0);
    asm volatile("cp.async.commit_group;\n");
    prefetch(1, GBK);
    asm volatile("cp.async.commit_group;\n");

    int rd = 0, wr = 2;
    for (int kt = 0; kt < KT; kt++) {
        asm volatile("cp.async.wait_group %0;\n" :: "n"(GSTAGES - 2));
        __syncthreads();   // all warps done with prior compute; stage rd data ready

        // prefetch next stage (overwrites stage read 1 iteration ago — safe post-sync)
        if (kt + GSTAGES - 1 < KT) prefetch(wr, (kt + GSTAGES - 1) * GBK);
        asm volatile("cp.async.commit_group;\n");

        const uint32_t* sA = sm + rd * STAGE_U32;
        const uint32_t* sB = sA + A_STAGE;

        #pragma unroll
        for (int ks = 0; ks < 4; ks++) {
            int kk = ks * 8 + q;
            uint32_t a[4][4];
            #pragma unroll
            for (int mt = 0; mt < 4; mt++) {
                const uint32_t* p = sA + (wm * 64 + mt * 16 + g) * A_STRIDE + kk;
                a[mt][0] = p[0];
                a[mt][1] = p[8 * A_STRIDE];
                a[mt][2] = p[4];
                a[mt][3] = p[8 * A_STRIDE + 4];
            }
            uint32_t b[4][2];
            #pragma unroll
            for (int nt = 0; nt < 4; nt++) {
                const uint32_t* p = sB + kk * B_STRIDE + wn * 32 + nt * 8 + g;
                b[nt][0] = p[0];
                b[nt][1] = p[4 * B_STRIDE];
            }
            #pragma unroll
            for (int mt = 0; mt < 4; mt++)
                #pragma unroll
                for (int nt = 0; nt < 4; nt++)
                    mma_f16(acc[mt][nt], a[mt][0], a[mt][1], a[mt][2], a[mt][3],
                            b[nt][0], b[nt][1]);
        }
        rd = (rd + 1 == GSTAGES) ? 0 : rd + 1;
        wr = (wr + 1 == GSTAGES) ? 0 : wr + 1;
    }

    // ---------------- epilogue ----------------
    #pragma unroll
    for (int nt = 0; nt < 4; nt++) {
        int c0 = bn + wn * 32 + nt * 8 + q * 2;
        float bb0 = 0.f, bb1 = 0.f;
        if (EP != 0) { bb0 = bias[c0]; bb1 = bias[c0 + 1]; }
        #pragma unroll
        for (int mt = 0; mt < 4; mt++) {
            #pragma unroll
            for (int half = 0; half < 2; half++) {
                int row = bm + wm * 64 + mt * 16 + g + half * 8;
                float v0 = acc[mt][nt][half * 2 + 0];
                float v1 = acc[mt][nt][half * 2 + 1];
                if (EP == 1) {
                    v0 += bb0; v1 += bb1;
                    float2 rr = *(const float2*)(resid + (size_t)row * N + c0);
                    v0 += rr.x; v1 += rr.y;
                }
                if (EP == 2) {
                    v0 += bb0; v1 += bb1;
                    v0 = 0.5f * v0 * (1.0f + erff(v0 * 0.70710678118654752f));
                    v1 = 0.5f * v1 * (1.0f + erff(v1 * 0.70710678118654752f));
                }
                if (OH) {
                    ((uint32_t*)Cout)[(size_t)row * (N / 2) + c0 / 2] = f2h2(v0, v1);
                } else {
                    float2 ov; ov.x = v0; ov.y = v1;
                    *(float2*)((float*)Cout + (size_t)row * N + c0) = ov;
                }
            }
        }
    }
}

// ---------------------------------------------------------------------------
// FP16 tensor-core causal flash attention (validated R15 version, unchanged).
// ---------------------------------------------------------------------------
constexpr int AQS = 36;   // sQ stride (u32/dpair), banks (4g+q) distinct
constexpr int AKS = 72;   // sKt/sV stride, banks (8q+g) distinct
constexpr int APS = 36;   // sP stride
__global__ __launch_bounds__(128) void attn_kernel(
    const uint32_t* __restrict__ qkv, uint32_t* __restrict__ O)
{
    __shared__ uint32_t sQ [64 * AQS];        // [row][dpair]
    __shared__ uint32_t sKt[32 * AKS];        // [dpair][j]
    __shared__ uint32_t sV [32 * AKS];        // [jpair][d(half col)]
    __shared__ uint32_t sPa[4 * 16 * APS];    // per-warp P [row][jpair]

    int tid = threadIdx.x;
    int w    = tid >> 5;
    int lane = tid & 31;
    int q    = lane & 3;
    int g    = lane >> 2;
    int m0   = w * 16;

    int ib  = blockIdx.x;
    int bh  = blockIdx.y;
    int b   = bh / NHh, h = bh % NHh;
    int rowbase = b * Tt + ib * 64;
    int qo2 = h * (HSz / 2);
    int ko2 = CU + qo2;
    int vo2 = 2 * CU + qo2;

    const float NEG_INF = __int_as_float(0xff800000);

    // ---- load Q tile (64 rows x 32 u32) ----
    #pragma unroll
    for (int i = 0; i < 4; i++) {
        int id = tid + i * 128;          // 0..511 uint4s
        int r  = id >> 3;
        int c4 = (id & 7) << 2;
        uint4 v = *(const uint4*)(qkv + (size_t)(rowbase + r) * QKVU + qo2 + c4);
        *(uint4*)(sQ + r * AQS + c4) = v;
    }
    __syncthreads();

    // ---- hoist Q fragments (warp-local rows) ----
    uint32_t aq[4][4];
    #pragma unroll
    for (int ks = 0; ks < 4; ks++) {
        const uint32_t* p = sQ + (m0 + g) * AQS + ks * 8 + q;
        aq[ks][0] = p[0];
        aq[ks][1] = p[8 * AQS];
        aq[ks][2] = p[4];
        aq[ks][3] = p[8 * AQS + 4];
    }
    uint32_t* sP = sPa + w * 16 * APS;

    float mA = NEG_INF, mB = NEG_INF, lA = 0.f, lB = 0.f;
    float o[8][4];
    #pragma unroll
    for (int nt = 0; nt < 8; nt++)
        #pragma unroll
        for (int r = 0; r < 4; r++) o[nt][r] = 0.f;

    const float scale = 0.03608439182435161f;   // 768^-0.5 (C, not hs)

    for (int jb = 0; jb <= ib; jb++) {
        if (jb) __syncthreads();
        int krow = b * Tt + jb * 64;
        // ---- K -> sKt[dpair][j] (transpose) ----
        #pragma unroll
        for (int i = 0; i < 4; i++) {
            int id = tid + i * 128;       // 0..511
            int r  = id & 63;             // row j
            int c4 = (id >> 6) << 2;      // dpair 0,4,..,28
            uint4 kv = *(const uint4*)(qkv + (size_t)(krow + r) * QKVU + ko2 + c4);
            sKt[(c4 + 0) * AKS + r] = kv.x;
            sKt[(c4 + 1) * AKS + r] = kv.y;
            sKt[(c4 + 2) * AKS + r] = kv.z;
            sKt[(c4 + 3) * AKS + r] = kv.w;
        }
        // ---- V -> sV[jpair][d half-col] (pair-pack along j) ----
        #pragma unroll
        for (int i = 0; i < 8; i++) {
            int id = tid + i * 128;       // 0..1023
            int jp = id >> 5;             // 0..31
            int dd = id & 31;             // dpair 0..31
            uint32_t x = qkv[(size_t)(krow + 2 * jp)     * QKVU + vo2 + dd];
            uint32_t y = qkv[(size_t)(krow + 2 * jp + 1) * QKVU + vo2 + dd];
            sV[jp * AKS + 2 * dd]     = __byte_perm(x, y, 0x5410);
            sV[jp * AKS + 2 * dd + 1] = __byte_perm(x, y, 0x7632);
        }
        __syncthreads();

        // ---- S = Q K^T ----
        float sacc[8][4];
        #pragma unroll
        for (int nt = 0; nt < 8; nt++)
            #pragma unroll
            for (int r = 0; r < 4; r++) sacc[nt][r] = 0.f;

        #pragma unroll
        for (int ks = 0; ks < 4; ks++) {
            int kk = ks * 8 + q;
            #pragma unroll
            for (int nt = 0; nt < 8; nt++) {
                uint32_t b0 = sKt[kk * AKS + nt * 8 + g];
                uint32_t b1 = sKt[(kk + 4) * AKS + nt * 8 + g];
                mma_f16(sacc[nt], aq[ks][0], aq[ks][1], aq[ks][2], aq[ks][3], b0, b1);
            }
        }

        // ---- scale + causal mask ----
        bool diag = (jb == ib);
        #pragma unroll
        for (int nt = 0; nt < 8; nt++) {
            #pragma unroll
            for (int r = 0; r < 4; r++) {
                float v = sacc[nt][r] * scale;
                if (diag) {
                    int lrow = m0 + g + ((r >= 2) ? 8 : 0);
                    int lcol = nt * 8 + 2 * q + (r & 1);
                    if (lcol > lrow) v = NEG_INF;
                }
                sacc[nt][r] = v;
            }
        }

        // ---- online softmax ----
        float bmaxA = NEG_INF, bmaxB = NEG_INF;
        #pragma unroll
        for (int nt = 0; nt < 8; nt++) {
            bmaxA = fmaxf(bmaxA, fmaxf(sacc[nt][0], sacc[nt][1]));
            bmaxB = fmaxf(bmaxB, fmaxf(sacc[nt][2], sacc[nt][3]));
        }
        #pragma unroll
        for (int off = 1; off < 4; off <<= 1) {
            bmaxA = fmaxf(bmaxA, __shfl_xor_sync(0xffffffffu, bmaxA, off));
            bmaxB = fmaxf(bmaxB, __shfl_xor_sync(0xffffffffu, bmaxB, off));
        }
        float mnA = fmaxf(mA, bmaxA), mnB = fmaxf(mB, bmaxB);
        float sumA = 0.f, sumB = 0.f;
        #pragma unroll
        for (int nt = 0; nt < 8; nt++) {
            float p0 = __expf(sacc[nt][0] - mnA);
            float p1 = __expf(sacc[nt][1] - mnA);
            float p2 = __expf(sacc[nt][2] - mnB);
            float p3 = __expf(sacc[nt][3] - mnB);
            sumA += p0 + p1; sumB += p2 + p3;
            sacc[nt][0] = p0; sacc[nt][1] = p1;
            sacc[nt][2] = p2; sacc[nt][3] = p3;
        }
        #pragma unroll
        for (int off = 1; off < 4; off <<= 1) {
            sumA += __shfl_xor_sync(0xffffffffu, sumA, off);
            sumB += __shfl_xor_sync(0xffffffffu, sumB, off);
        }
        float alphaA = __expf(mA - mnA), alphaB = __expf(mB - mnB);
        lA = lA * alphaA + sumA; lB = lB * alphaB + sumB;
        mA = mnA; mB = mnB;
        #pragma unroll
        for (int nt = 0; nt < 8; nt++) {
            o[nt][0] *= alphaA; o[nt][1] *= alphaA;
            o[nt][2] *= alphaB; o[nt][3] *= alphaB;
        }

        // ---- P (half2 pairs) -> warp-local sP[row][jpair] ----
        #pragma unroll
        for (int nt = 0; nt < 8; nt++) {
            sP[g * APS + nt * 4 + q]       = f2h2(sacc[nt][0], sacc[nt][1]);
            sP[(g + 8) * APS + nt * 4 + q] = f2h2(sacc[nt][2], sacc[nt][3]);
        }
        __syncwarp();

        // ---- O += P V ----
        #pragma unroll
        for (int ks = 0; ks < 4; ks++) {
            int kk = ks * 8 + q;
            const uint32_t* pp = sP + g * APS + kk;
            uint32_t a0 = pp[0];
            uint32_t a1 = pp[8 * APS];
            uint32_t a2 = pp[4];
            uint32_t a3 = pp[8 * APS + 4];
            #pragma unroll
            for (int nt = 0; nt < 8; nt++) {
                uint32_t b0 = sV[kk * AKS + nt * 8 + g];
                uint32_t b1 = sV[(kk + 4) * AKS + nt * 8 + g];
                mma_f16(o[nt], a0, a1, a2, a3, b0, b1);
            }
        }
        __syncwarp();
    }

    // ---- epilogue: normalize, store half2 ----
    float invA = 1.0f / lA, invB = 1.0f / lB;
    #pragma unroll
    for (int nt = 0; nt < 8; nt++) {
        int colp = h * (HSz / 2) + nt * 4 + q;   // u32 column
        int rA = rowbase + m0 + g;
        int rB = rA + 8;
        O[(size_t)rA * CU + colp] = f2h2(o[nt][0] * invA, o[nt][1] * invA);
        O[(size_t)rB * CU + colp] = f2h2(o[nt][2] * invB, o[nt][3] * invB);
    }
}

// ---------------------------------------------------------------------------
// Launch
// ---------------------------------------------------------------------------
extern "C" void kernel_launch(void* const* d_in, const int* in_sizes, int n_in,
                              void* d_out, int out_size)
{
    const float* x   = (const float*)d_in[0];
    const float* Wq  = (const float*)d_in[1];
    const float* Wk  = (const float*)d_in[2];
    const float* Wv  = (const float*)d_in[3];
    const float* Wo  = (const float*)d_in[4];
    const float* bo  = (const float*)d_in[5];
    const float* W1  = (const float*)d_in[6];
    const float* b1  = (const float*)d_in[7];
    const float* W2  = (const float*)d_in[8];
    const float* b2  = (const float*)d_in[9];
    const float* g1  = (const float*)d_in[10];
    const float* be1 = (const float*)d_in[11];
    const float* g2  = (const float*)d_in[12];
    const float* be2 = (const float*)d_in[13];
    float* out = (float*)d_out;

    uint32_t *h, *qkv, *o, *h2, *ff, *wqkv, *wo, *w1, *w2;
    float *x2;
    cudaGetSymbolAddress((void**)&h,    g_h);
    cudaGetSymbolAddress((void**)&qkv,  g_qkv);
    cudaGetSymbolAddress((void**)&o,    g_o);
    cudaGetSymbolAddress((void**)&x2,   g_x2);
    cudaGetSymbolAddress((void**)&h2,   g_h2);
    cudaGetSymbolAddress((void**)&ff,   g_ff);
    cudaGetSymbolAddress((void**)&wqkv, g_wqkv);
    cudaGetSymbolAddress((void**)&wo,   g_wo);
    cudaGetSymbolAddress((void**)&w1,   g_w1);
    cudaGetSymbolAddress((void**)&w2,   g_w2);

    cudaFuncSetAttribute(gemm_tc<0,1>,
        cudaFuncAttributeMaxDynamicSharedMemorySize, GEMM_SMEM);
    cudaFuncSetAttribute(gemm_tc<1,0>,
        cudaFuncAttributeMaxDynamicSharedMemorySize, GEMM_SMEM);
    cudaFuncSetAttribute(gemm_tc<2,1>,
        cudaFuncAttributeMaxDynamicSharedMemorySize, GEMM_SMEM);

    dim3 blk(256);
    dim3 g768 (Cc   / 128, MR / 128);   // (6, 64)
    dim3 gqkv (QKVN / 128, MR / 128);   // (18, 64)
    dim3 g3072(FFd  / 128, MR / 128);   // (24, 64)

    // ---- weight conversion fp32 -> packed half2 k-pairs ----
    int tCC = CU * Cc;     // 294912
    int tCF = CU * FFd;    // 1179648
    int tFC = FFU * Cc;    // 1179648
    cvt_pack_kernel<<<(tCC + 255) / 256, blk>>>(Wq, wqkv, Cc, QKVN, 0,      tCC);
    cvt_pack_kernel<<<(tCC + 255) / 256, blk>>>(Wk, wqkv, Cc, QKVN, Cc,     tCC);
    cvt_pack_kernel<<<(tCC + 255) / 256, blk>>>(Wv, wqkv, Cc, QKVN, 2 * Cc, tCC);
    cvt_pack_kernel<<<(tCC + 255) / 256, blk>>>(Wo, wo,   Cc, Cc,   0,      tCC);
    cvt_pack_kernel<<<(tCF + 255) / 256, blk>>>(W1, w1,   FFd, FFd, 0,      tCF);
    cvt_pack_kernel<<<(tFC + 255) / 256, blk>>>(W2, w2,   Cc,  Cc,  0,      tFC);

    // h = LN(x) (fp16)
    ln_kernel<<<MR / 8, blk>>>(x, g1, be1, h);
    // qkv = h @ [Wq|Wk|Wv]  (fp16 out)
    gemm_tc<0,1><<<gqkv, blk, GEMM_SMEM>>>(h, wqkv, nullptr, nullptr, qkv, MR, QKVN, CU);
    // causal attention (fp16 out)
    attn_kernel<<<dim3(Tt / 64, Bb * NHh), dim3(128)>>>(qkv, o);
    // x2 = x + o @ Wo + bo (fp32 out)
    gemm_tc<1,0><<<g768, blk, GEMM_SMEM>>>(o, wo, bo, x, x2, MR, Cc, CU);
    // h2 = LN(x2) (fp16)
    ln_kernel<<<MR / 8, blk>>>(x2, g2, be2, h2);
    // ff = gelu(h2 @ W1 + b1) (fp16 out)
    gemm_tc<2,1><<<g3072, blk, GEMM_SMEM>>>(h2, w1, b1, nullptr, ff, MR, FFd, CU);
    // out = x2 + ff @ W2 + b2 (fp32 out)
    gemm_tc<1,0><<<g768, blk, GEMM_SMEM>>>(ff, w2, b2, x2, out, MR, Cc, FFU);
}